// round 15
// baseline (speedup 1.0000x reference)
#include <cuda_runtime.h>
#include <cuda_fp16.h>
#include <cstdint>
#include <cstddef>

// Persistent 1-term fp16 HMMA LSTM. 128 CTAs x 512 threads.
// R15 = R14 bulk-staging engine + R13 k-split warp tiling:
//   16 warps = 4 M-subtiles(32) x 2 N-halves(32) x 2 K-halves(64k).
//   Per chunk/warp: 16 ldm4 + 32 HMMA (smem reads 196KB -> 128KB per chunk).
//   Once-per-phase cross-K partner reduction through stage-0 smem.
#define Bsz 256
#define Hdim 1024
#define Tlen 336
#define OUTLEN 96
#define BH (Bsz*Hdim)
#define NCTA 128
#define NTHR 512
#define STG 49152                 // stage: A 32KB (128x256B) + W 16KB (64x256B)
#define OFF_W 32768
#define NSTG 4
#define MB_OFF (NSTG*STG)         // 4 mbarriers (8B each)
#define SMEM_TOTAL (NSTG*STG + 64)

// Pre-swizzled images. A: [chunk 8][m 256][256B]; W: [ntile 64][chunk 8][row 64][256B].
__device__ __align__(128) uint8_t g_Aimg[2][2][524288];     // [layer][ping]
__device__ __align__(128) uint8_t g_Wimg[6][8388608];
__device__ float g_c0[BH], g_c1[BH], g_h1f[BH], g_xt[Bsz];
__device__ unsigned g_cnt, g_gen;

__device__ __forceinline__ uint32_t smem_u32(const void* p) {
    uint32_t a;
    asm("{ .reg .u64 t; cvta.to.shared.u64 t, %1; cvt.u32.u64 %0, t; }" : "=r"(a) : "l"(p));
    return a;
}
__device__ __forceinline__ void bulk_g2s(uint32_t dst, const void* src, uint32_t bytes, uint32_t mbar) {
    asm volatile(
        "cp.async.bulk.shared::cluster.global.mbarrier::complete_tx::bytes [%0], [%1], %2, [%3];"
        :: "r"(dst), "l"(src), "r"(bytes), "r"(mbar) : "memory");
}
__device__ __forceinline__ void mbar_init(uint32_t a, uint32_t c) {
    asm volatile("mbarrier.init.shared.b64 [%0], %1;" :: "r"(a), "r"(c) : "memory");
}
__device__ __forceinline__ void mbar_expect_tx(uint32_t a, uint32_t bytes) {
    asm volatile("mbarrier.arrive.expect_tx.shared.b64 _, [%0], %1;" :: "r"(a), "r"(bytes) : "memory");
}
__device__ __forceinline__ void mbar_wait(uint32_t a, uint32_t par) {
    uint32_t done;
    asm volatile("{\n\t.reg .pred p;\n\t"
        "mbarrier.try_wait.parity.acquire.cta.shared::cta.b64 p, [%1], %2;\n\t"
        "selp.b32 %0, 1, 0, p;\n\t}" : "=r"(done) : "r"(a), "r"(par) : "memory");
    if (!done) {
        asm volatile("{\n\t.reg .pred P1;\n\tW_%=:\n\t"
            "mbarrier.try_wait.parity.acquire.cta.shared::cta.b64 P1, [%0], %1, 0x989680;\n\t"
            "@P1 bra.uni D_%=;\n\tbra.uni W_%=;\n\tD_%=:\n\t}" :: "r"(a), "r"(par) : "memory");
    }
}
__device__ __forceinline__ void ldm4(uint32_t* r, uint32_t a) {
    asm volatile("ldmatrix.sync.aligned.m8n8.x4.shared.b16 {%0,%1,%2,%3}, [%4];"
        : "=r"(r[0]), "=r"(r[1]), "=r"(r[2]), "=r"(r[3]) : "r"(a));
}
__device__ __forceinline__ void mma16816(float* c, const uint32_t* a, uint32_t b0, uint32_t b1) {
    asm volatile(
        "mma.sync.aligned.m16n8k16.row.col.f32.f16.f16.f32 "
        "{%0,%1,%2,%3}, {%4,%5,%6,%7}, {%8,%9}, {%0,%1,%2,%3};"
        : "+f"(c[0]), "+f"(c[1]), "+f"(c[2]), "+f"(c[3])
        : "r"(a[0]), "r"(a[1]), "r"(a[2]), "r"(a[3]), "r"(b0), "r"(b1));
}
__device__ __forceinline__ float sigmoidf_(float x) { return 1.0f / (1.0f + expf(-x)); }

__device__ __forceinline__ void grid_sync() {
    __syncthreads();
    if (threadIdx.x == 0) {
        __threadfence();
        unsigned g = *(volatile unsigned*)&g_gen;
        unsigned a = atomicAdd(&g_cnt, 1u);
        if (a == NCTA - 1) {
            atomicExch(&g_cnt, 0u);
            __threadfence();
            atomicAdd(&g_gen, 1u);
        } else {
            while (*(volatile unsigned*)&g_gen == g) { __nanosleep(64); }
        }
        __threadfence();
    }
    __syncthreads();
}

// SW128-style XOR on the 16B segment index within a 256B row.
__device__ __forceinline__ uint32_t physseg(uint32_t seg, uint32_t row) {
    return (seg & 8u) | ((seg & 7u) ^ (row & 7u));
}

// Weights -> swizzled images. col = (hid>>4)*64 + ((hid>>3)&1)*32 + gate*8 + (hid&7).
__device__ void prologue(const float* const* Ws, const float* x) {
    const int gt = blockIdx.x * NTHR + threadIdx.x;
#pragma unroll 1
    for (int mat = 0; mat < 6; mat++) {
        const float* src = Ws[mat];
#pragma unroll 1
        for (int p = gt; p < (4096 * 1024 / 2); p += NCTA * NTHR) {
            int gr = p >> 9;
            int k  = (p & 511) << 1;
            float2 v = *(const float2*)(src + (size_t)gr * 1024 + k);
            int gate = gr >> 10, hid = gr & 1023;
            int col = (hid >> 4) * 64 + ((hid >> 3) & 1) * 32 + gate * 8 + (hid & 7);
            uint32_t nt = (uint32_t)col >> 6, r = (uint32_t)col & 63;
            uint32_t c = (uint32_t)k >> 7, koff = (uint32_t)k & 127;
            size_t off = (size_t)(((nt << 3) + c) << 14) + r * 256
                       + physseg(koff >> 3, r) * 16 + (koff & 7) * 2;
            __half h0 = __float2half_rn(v.x);
            __half h1 = __float2half_rn(v.y);
            *(uint32_t*)&g_Wimg[mat][off] =
                (uint32_t)__half_as_ushort(h0) | ((uint32_t)__half_as_ushort(h1) << 16);
        }
    }
    float4 zf = make_float4(0.f, 0.f, 0.f, 0.f);
    uint4 z4 = make_uint4(0, 0, 0, 0);
    for (int i = gt; i < BH / 4; i += NCTA * NTHR) {
        ((float4*)g_c0)[i] = zf;
        ((float4*)g_c1)[i] = zf;
    }
    for (int i = gt; i < 524288 / 16; i += NCTA * NTHR) {
        ((uint4*)g_Aimg[0][0])[i] = z4;
        ((uint4*)g_Aimg[1][0])[i] = z4;
    }
    if (gt < Bsz) g_xt[gt] = x[(size_t)gt * Tlen + (Tlen - 1)];
}

// One recurrence phase: D(128x64) = sum over passes A@W^T, fused LSTM pointwise.
// Warp wrp: M-subtile wm=wrp&3 (32 rows), N-half wn=(wrp>>2)&1, K-half kh=wrp>>3.
__device__ __noinline__ void lstm_phase(
    uint32_t tb, int npass,
    const uint8_t* A0, const uint8_t* W0,
    const uint8_t* A1, const uint8_t* W1,
    const float* __restrict__ bias, const float* __restrict__ wih,
    const float* __restrict__ xs, int xs_stride,
    float* __restrict__ cst,
    uint8_t* __restrict__ oA, float* __restrict__ of32, int* par)
{
    const int tid = threadIdx.x;
    const int m_t = blockIdx.x & 1;
    const int n_t = blockIdx.x >> 1;
    const int C = npass << 3;               // 8 chunks of K=128 per pass
    const uint32_t mb = tb + MB_OFF;

    auto prefetch = [&](int j) {            // tid 0 only
        const int pass = j >> 3, c = j & 7;
        const int s = j & 3;
        const uint8_t* ai = pass ? A1 : A0;
        const uint8_t* wi = pass ? W1 : W0;
        mbar_expect_tx(mb + s * 8, STG);
        bulk_g2s(tb + s * STG, ai + (size_t)((c * 256 + m_t * 128) << 8), 32768, mb + s * 8);
        bulk_g2s(tb + s * STG + OFF_W, wi + (size_t)(((n_t << 3) + c) << 14), 16384, mb + s * 8);
    };

    const int lane = tid & 31, wrp = tid >> 5;
    const int wm = wrp & 3, wn = (wrp >> 2) & 1, kh = wrp >> 3;
    const int mat = lane >> 3, rr = lane & 7;
    const uint32_t aRow = wm * 32 + (mat & 1) * 8 + rr;     // M-frag 0; frag 1 = +16 rows
    const uint32_t aSeg0 = (uint32_t)(mat >> 1) + kh * 8;
    const uint32_t bRow = wn * 32 + (mat >> 1) * 8 + rr;    // + q*16
    const uint32_t bSeg0 = (uint32_t)(mat & 1) + kh * 8;

    float acc[2][4][4];                     // [M-frag][gate][elem]
#pragma unroll
    for (int a = 0; a < 2; a++)
#pragma unroll
        for (int j = 0; j < 4; j++)
#pragma unroll
            for (int e = 0; e < 4; e++) acc[a][j][e] = 0.0f;

    if (tid == 0) { prefetch(0); prefetch(1); prefetch(2); }

#pragma unroll 1
    for (int ch = 0; ch < C; ch++) {
        __syncthreads();                    // prior chunk fully read -> stage free
        if (tid == 0 && ch + 3 < C) prefetch(ch + 3);
        const int s = ch & 3;
        mbar_wait(mb + s * 8, (uint32_t)(par[s] & 1));
        par[s]++;
        const uint32_t sa = tb + s * STG;
#pragma unroll
        for (int ks = 0; ks < 4; ks++) {    // 4 k16 steps within this warp's 64-k half
            uint32_t aF[2][4];
            uint32_t segA = (uint32_t)(ks * 2) + aSeg0;
            ldm4(aF[0], sa + aRow * 256 + physseg(segA, aRow & 7) * 16);
            ldm4(aF[1], sa + (aRow + 16) * 256 + physseg(segA, (aRow + 16) & 7) * 16);
#pragma unroll
            for (int q = 0; q < 2; q++) {
                uint32_t b4[4];
                uint32_t segB = (uint32_t)(ks * 2) + bSeg0;
                uint32_t br = bRow + q * 16;
                ldm4(b4, sa + OFF_W + br * 256 + physseg(segB, br & 7) * 16);
                mma16816(acc[0][2 * q],     aF[0], b4[0], b4[1]);
                mma16816(acc[0][2 * q + 1], aF[0], b4[2], b4[3]);
                mma16816(acc[1][2 * q],     aF[1], b4[0], b4[1]);
                mma16816(acc[1][2 * q + 1], aF[1], b4[2], b4[3]);
            }
        }
    }

    // ---- cross-K reduction: partner warps (kh <-> kh^1) swap one M-frag half.
    // Warp keeps frag am=kh (rows wm*32+kh*16..+16) and gives away am=kh^1.
    __syncthreads();                        // all stage reads done; reuse stage smem
    {
        float* red = (float*)0 + 0;         // (silence unused warn pattern)
        (void)red;
        float* buf = (float*)(uintptr_t)0;  // not used; smem addressed via tb below
        (void)buf;
    }
    {
        // slot layout: [pair 8][kh 2][lane 32][16 floats] = 32KB at stage 0
        const uint32_t slot = tb + ((((uint32_t)(wrp & 7) * 2 + (uint32_t)kh) * 32
                                     + (uint32_t)lane) * 16) * 4;
        const int gv = kh ^ 1;
#pragma unroll
        for (int j = 0; j < 4; j++) {
            float4 v = make_float4(acc[gv][j][0], acc[gv][j][1], acc[gv][j][2], acc[gv][j][3]);
            asm volatile("st.shared.v4.f32 [%0], {%1,%2,%3,%4};"
                :: "r"(slot + j * 16), "f"(v.x), "f"(v.y), "f"(v.z), "f"(v.w) : "memory");
        }
    }
    __syncthreads();
    {
        const uint32_t psl = tb + ((((uint32_t)(wrp & 7) * 2 + (uint32_t)(kh ^ 1)) * 32
                                    + (uint32_t)lane) * 16) * 4;
#pragma unroll
        for (int j = 0; j < 4; j++) {
            float x0, x1, x2, x3;
            asm volatile("ld.shared.v4.f32 {%0,%1,%2,%3}, [%4];"
                : "=f"(x0), "=f"(x1), "=f"(x2), "=f"(x3) : "r"(psl + j * 16));
            acc[kh][j][0] += x0; acc[kh][j][1] += x1;
            acc[kh][j][2] += x2; acc[kh][j][3] += x3;
        }
    }
    __syncthreads();                        // reduction buffer free before next prefetch

    // ---- epilogue: acc[kh][j] = gate j; thread owns 2 rows x 2 hids ----
    const int grp = lane >> 2, tig = lane & 3;
    const int hid0 = n_t * 16 + wn * 8 + 2 * tig;
#pragma unroll
    for (int s = 0; s < 2; s++) {
        int mm = m_t * 128 + wm * 32 + kh * 16 + grp + 8 * s;
        float xv = xs ? xs[(size_t)mm * xs_stride] : 0.0f;
        float hn[2];
#pragma unroll
        for (int d = 0; d < 2; d++) {
            int e = 2 * s + d;
            int hd = hid0 + d;
            float pi = acc[kh][0][e] + bias[hd]        + (wih ? xv * wih[hd]        : 0.f);
            float pf = acc[kh][1][e] + bias[1024 + hd] + (wih ? xv * wih[1024 + hd] : 0.f);
            float pg = acc[kh][2][e] + bias[2048 + hd] + (wih ? xv * wih[2048 + hd] : 0.f);
            float po = acc[kh][3][e] + bias[3072 + hd] + (wih ? xv * wih[3072 + hd] : 0.f);
            size_t cix = (size_t)mm * Hdim + hd;
            float cn = sigmoidf_(pf) * cst[cix] + sigmoidf_(pi) * tanhf(pg);
            hn[d] = sigmoidf_(po) * tanhf(cn);
            cst[cix] = cn;
        }
        // write into swizzled A image: [chunk][m 0..255][256B]
        uint32_t c = (uint32_t)hid0 >> 7, koff = (uint32_t)hid0 & 127;
        size_t aoff = (size_t)((c * 256 + (uint32_t)mm) << 8)
                    + physseg(koff >> 3, (uint32_t)mm) * 16 + (koff & 7) * 2;
        __half h0 = __float2half_rn(hn[0]);
        __half h1 = __float2half_rn(hn[1]);
        *(uint32_t*)&oA[aoff] =
            (uint32_t)__half_as_ushort(h0) | ((uint32_t)__half_as_ushort(h1) << 16);
        if (of32) *(float2*)&of32[(size_t)mm * Hdim + hid0] = make_float2(hn[0], hn[1]);
    }
}

__device__ __forceinline__ void fc_phase(
    const float* __restrict__ h1, const float* __restrict__ fcW,
    const float* __restrict__ fcb, float* __restrict__ out, int s)
{
    if (blockIdx.x >= 16) return;           // 16 CTAs x 16 warps = 256 rows
    int warp = threadIdx.x >> 5, lane = threadIdx.x & 31;
    int b = blockIdx.x * 16 + warp;
    float sum = 0.0f;
    const float* hr = h1 + (size_t)b * Hdim;
#pragma unroll 8
    for (int k = lane; k < Hdim; k += 32) sum += hr[k] * fcW[k];
#pragma unroll
    for (int o = 16; o > 0; o >>= 1) sum += __shfl_down_sync(0xFFFFFFFFu, sum, o);
    if (lane == 0) {
        float y = sum + fcb[0];
        out[(size_t)b * OUTLEN + s] = y;
        g_xt[b] = y;
    }
}

__global__ void __launch_bounds__(NTHR, 1) lstm_mma_kernel(
    const float* __restrict__ x,
    const float* eWih0, const float* eWhh0, const float* eb0,
    const float* eWih1, const float* eWhh1, const float* eb1,
    const float* dWih0, const float* dWhh0, const float* db0,
    const float* dWih1, const float* dWhh1, const float* db1,
    const float* fcW, const float* fcb, float* __restrict__ out)
{
    extern __shared__ uint8_t dsm[];
    const uint32_t tb = smem_u32(dsm);

    if (threadIdx.x == 0) {
        mbar_init(tb + MB_OFF + 0, 1);
        mbar_init(tb + MB_OFF + 8, 1);
        mbar_init(tb + MB_OFF + 16, 1);
        mbar_init(tb + MB_OFF + 24, 1);
    }
    const float* Ws[6] = { eWhh0, eWih1, eWhh1, dWhh0, dWih1, dWhh1 };
    prologue(Ws, x);
    grid_sync();                            // also publishes mbarrier init

    int par[NSTG] = { 0, 0, 0, 0 };
    int p0 = 0, p1 = 0;

#pragma unroll 1
    for (int t = 0; t < Tlen; t++) {
        lstm_phase(tb, 1,
            g_Aimg[0][p0], g_Wimg[0], nullptr, nullptr,
            eb0, eWih0, x + t, Tlen, g_c0,
            g_Aimg[0][p0 ^ 1], nullptr, par);
        p0 ^= 1;
        grid_sync();
        lstm_phase(tb, 2,
            g_Aimg[0][p0], g_Wimg[1], g_Aimg[1][p1], g_Wimg[2],
            eb1, nullptr, nullptr, 0, g_c1,
            g_Aimg[1][p1 ^ 1], nullptr, par);
        p1 ^= 1;
        grid_sync();
    }
#pragma unroll 1
    for (int s = 0; s < OUTLEN; s++) {
        lstm_phase(tb, 1,
            g_Aimg[0][p0], g_Wimg[3], nullptr, nullptr,
            db0, dWih0, g_xt, 1, g_c0,
            g_Aimg[0][p0 ^ 1], nullptr, par);
        p0 ^= 1;
        grid_sync();
        lstm_phase(tb, 2,
            g_Aimg[0][p0], g_Wimg[4], g_Aimg[1][p1], g_Wimg[5],
            db1, nullptr, nullptr, 0, g_c1,
            g_Aimg[1][p1 ^ 1], g_h1f, par);
        p1 ^= 1;
        grid_sync();
        fc_phase(g_h1f, fcW, fcb, out, s);
        grid_sync();
    }
}

extern "C" void kernel_launch(void* const* d_in, const int* in_sizes, int n_in,
                              void* d_out, int out_size)
{
    (void)in_sizes; (void)n_in; (void)out_size;
    cudaFuncSetAttribute(lstm_mma_kernel, cudaFuncAttributeMaxDynamicSharedMemorySize, SMEM_TOTAL);
    lstm_mma_kernel<<<NCTA, NTHR, SMEM_TOTAL>>>(
        (const float*)d_in[0],
        (const float*)d_in[1],  (const float*)d_in[2],  (const float*)d_in[3],
        (const float*)d_in[4],  (const float*)d_in[5],  (const float*)d_in[6],
        (const float*)d_in[7],  (const float*)d_in[8],  (const float*)d_in[9],
        (const float*)d_in[10], (const float*)d_in[11], (const float*)d_in[12],
        (const float*)d_in[13], (const float*)d_in[14],
        (float*)d_out);
}

// round 16
// speedup vs baseline: 1.1280x; 1.1280x over previous
#include <cuda_runtime.h>
#include <cuda_fp16.h>
#include <cstdint>
#include <cstddef>

// Persistent 1-term fp16 HMMA LSTM. 128 CTAs x 512 threads, warp tile 16x32.
// R16 = R14 engine + (a) K=256 super-chunks: 2x R14 chunk body per sync-unit,
// 2 stages x 96KB, prefetch depth 1, 3 bulk copies/unit; (b) per-M-half grid
// barriers (batch halves are independent; FC done per-half by 8 CTAs/half).
#define Bsz 256
#define Hdim 1024
#define Tlen 336
#define OUTLEN 96
#define BH (Bsz*Hdim)
#define NCTA 128
#define NTHR 512
#define STG 98304                 // stage: A 2x32KB + W 2x16KB
#define OFF_W 65536
#define NSTG 2
#define MB_OFF (NSTG*STG)         // 2 mbarriers
#define SMEM_TOTAL (NSTG*STG + 64)

// Pre-swizzled images. A: [chunk 8][m 256][256B]; W: [ntile 64][chunk 8][row 64][256B].
__device__ __align__(128) uint8_t g_Aimg[2][2][524288];     // [layer][ping]
__device__ __align__(128) uint8_t g_Wimg[6][8388608];
__device__ float g_c0[BH], g_c1[BH], g_h1f[BH], g_xt[Bsz];
__device__ unsigned g_bar[3][64];   // [id][0]=cnt, [id][32]=gen; id 0/1 = M-half, 2 = full

__device__ __forceinline__ uint32_t smem_u32(const void* p) {
    uint32_t a;
    asm("{ .reg .u64 t; cvta.to.shared.u64 t, %1; cvt.u32.u64 %0, t; }" : "=r"(a) : "l"(p));
    return a;
}
__device__ __forceinline__ void bulk_g2s(uint32_t dst, const void* src, uint32_t bytes, uint32_t mbar) {
    asm volatile(
        "cp.async.bulk.shared::cluster.global.mbarrier::complete_tx::bytes [%0], [%1], %2, [%3];"
        :: "r"(dst), "l"(src), "r"(bytes), "r"(mbar) : "memory");
}
__device__ __forceinline__ void mbar_init(uint32_t a, uint32_t c) {
    asm volatile("mbarrier.init.shared.b64 [%0], %1;" :: "r"(a), "r"(c) : "memory");
}
__device__ __forceinline__ void mbar_expect_tx(uint32_t a, uint32_t bytes) {
    asm volatile("mbarrier.arrive.expect_tx.shared.b64 _, [%0], %1;" :: "r"(a), "r"(bytes) : "memory");
}
__device__ __forceinline__ void mbar_wait(uint32_t a, uint32_t par) {
    uint32_t done;
    asm volatile("{\n\t.reg .pred p;\n\t"
        "mbarrier.try_wait.parity.acquire.cta.shared::cta.b64 p, [%1], %2;\n\t"
        "selp.b32 %0, 1, 0, p;\n\t}" : "=r"(done) : "r"(a), "r"(par) : "memory");
    if (!done) {
        asm volatile("{\n\t.reg .pred P1;\n\tW_%=:\n\t"
            "mbarrier.try_wait.parity.acquire.cta.shared::cta.b64 P1, [%0], %1, 0x989680;\n\t"
            "@P1 bra.uni D_%=;\n\tbra.uni W_%=;\n\tD_%=:\n\t}" :: "r"(a), "r"(par) : "memory");
    }
}
__device__ __forceinline__ void ldm4(uint32_t* r, uint32_t a) {
    asm volatile("ldmatrix.sync.aligned.m8n8.x4.shared.b16 {%0,%1,%2,%3}, [%4];"
        : "=r"(r[0]), "=r"(r[1]), "=r"(r[2]), "=r"(r[3]) : "r"(a));
}
__device__ __forceinline__ void mma16816(float* c, const uint32_t* a, uint32_t b0, uint32_t b1) {
    asm volatile(
        "mma.sync.aligned.m16n8k16.row.col.f32.f16.f16.f32 "
        "{%0,%1,%2,%3}, {%4,%5,%6,%7}, {%8,%9}, {%0,%1,%2,%3};"
        : "+f"(c[0]), "+f"(c[1]), "+f"(c[2]), "+f"(c[3])
        : "r"(a[0]), "r"(a[1]), "r"(a[2]), "r"(a[3]), "r"(b0), "r"(b1));
}
__device__ __forceinline__ float sigmoidf_(float x) { return 1.0f / (1.0f + expf(-x)); }

// Grid barrier over n CTAs; id selects independent cnt/gen (separate lines).
__device__ __forceinline__ void gsync(int id, unsigned n) {
    __syncthreads();
    if (threadIdx.x == 0) {
        __threadfence();
        unsigned g = *(volatile unsigned*)&g_bar[id][32];
        unsigned a = atomicAdd(&g_bar[id][0], 1u);
        if (a == n - 1) {
            atomicExch(&g_bar[id][0], 0u);
            __threadfence();
            atomicAdd(&g_bar[id][32], 1u);
        } else {
            while (*(volatile unsigned*)&g_bar[id][32] == g) { __nanosleep(64); }
        }
        __threadfence();
    }
    __syncthreads();
}

// SW128-style XOR on the 16B segment index within a 256B row.
__device__ __forceinline__ uint32_t physseg(uint32_t seg, uint32_t row) {
    return (seg & 8u) | ((seg & 7u) ^ (row & 7u));
}

// Weights -> swizzled images. col = (hid>>4)*64 + ((hid>>3)&1)*32 + gate*8 + (hid&7).
__device__ void prologue(const float* const* Ws, const float* x) {
    const int gt = blockIdx.x * NTHR + threadIdx.x;
#pragma unroll 1
    for (int mat = 0; mat < 6; mat++) {
        const float* src = Ws[mat];
#pragma unroll 1
        for (int p = gt; p < (4096 * 1024 / 2); p += NCTA * NTHR) {
            int gr = p >> 9;
            int k  = (p & 511) << 1;
            float2 v = *(const float2*)(src + (size_t)gr * 1024 + k);
            int gate = gr >> 10, hid = gr & 1023;
            int col = (hid >> 4) * 64 + ((hid >> 3) & 1) * 32 + gate * 8 + (hid & 7);
            uint32_t nt = (uint32_t)col >> 6, r = (uint32_t)col & 63;
            uint32_t c = (uint32_t)k >> 7, koff = (uint32_t)k & 127;
            size_t off = (size_t)(((nt << 3) + c) << 14) + r * 256
                       + physseg(koff >> 3, r) * 16 + (koff & 7) * 2;
            __half h0 = __float2half_rn(v.x);
            __half h1 = __float2half_rn(v.y);
            *(uint32_t*)&g_Wimg[mat][off] =
                (uint32_t)__half_as_ushort(h0) | ((uint32_t)__half_as_ushort(h1) << 16);
        }
    }
    float4 zf = make_float4(0.f, 0.f, 0.f, 0.f);
    uint4 z4 = make_uint4(0, 0, 0, 0);
    for (int i = gt; i < BH / 4; i += NCTA * NTHR) {
        ((float4*)g_c0)[i] = zf;
        ((float4*)g_c1)[i] = zf;
    }
    for (int i = gt; i < 524288 / 16; i += NCTA * NTHR) {
        ((uint4*)g_Aimg[0][0])[i] = z4;
        ((uint4*)g_Aimg[1][0])[i] = z4;
    }
    if (gt < Bsz) g_xt[gt] = x[(size_t)gt * Tlen + (Tlen - 1)];
}

// One recurrence phase: D(128x64) = sum over passes A@W^T, fused LSTM pointwise.
// Super-chunks of K=256 (two k128 image chunks per sync-unit).
__device__ __noinline__ void lstm_phase(
    uint32_t tb, int npass,
    const uint8_t* A0, const uint8_t* W0,
    const uint8_t* A1, const uint8_t* W1,
    const float* __restrict__ bias, const float* __restrict__ wih,
    const float* __restrict__ xs, int xs_stride,
    float* __restrict__ cst,
    uint8_t* __restrict__ oA, float* __restrict__ of32, int* par)
{
    const int tid = threadIdx.x;
    const int m_t = blockIdx.x & 1;
    const int n_t = blockIdx.x >> 1;
    const int C = npass << 2;               // 4 super-chunks (K=256) per pass
    const uint32_t mb = tb + MB_OFF;

    auto prefetch = [&](int j) {            // tid 0 only
        const int pass = j >> 2, c2 = j & 3;
        const int s = j & 1;
        const uint8_t* ai = pass ? A1 : A0;
        const uint8_t* wi = pass ? W1 : W0;
        mbar_expect_tx(mb + s * 8, STG);
        const int cc = c2 * 2;
        bulk_g2s(tb + s * STG,
                 ai + (size_t)((cc * 256 + m_t * 128) << 8), 32768, mb + s * 8);
        bulk_g2s(tb + s * STG + 32768,
                 ai + (size_t)(((cc + 1) * 256 + m_t * 128) << 8), 32768, mb + s * 8);
        bulk_g2s(tb + s * STG + OFF_W,
                 wi + (size_t)(((n_t << 3) + cc) << 14), 32768, mb + s * 8);
    };

    const int lane = tid & 31, w = tid >> 5;
    const int wm = w & 7, wn = w >> 3;
    const int mat = lane >> 3, rr = lane & 7;
    const uint32_t aRow = wm * 16 + (mat & 1) * 8 + rr;
    const uint32_t aSeg0 = (uint32_t)(mat >> 1);
    const uint32_t aXor = aRow & 7;
    const uint32_t bRow = wn * 32 + (mat >> 1) * 8 + rr;    // + q*16 (low 3 bits same)
    const uint32_t bSeg0 = (uint32_t)(mat & 1);
    const uint32_t bXor = bRow & 7;

    float acc[4][4];
#pragma unroll
    for (int j = 0; j < 4; j++)
#pragma unroll
        for (int e = 0; e < 4; e++) acc[j][e] = 0.0f;

    if (tid == 0) prefetch(0);

#pragma unroll 1
    for (int ch = 0; ch < C; ch++) {
        __syncthreads();                    // reads of chunk ch-1 done -> its stage free
        if (tid == 0 && ch + 1 < C) prefetch(ch + 1);
        const int s = ch & 1;
        mbar_wait(mb + s * 8, (uint32_t)(par[s] & 1));
        par[s]++;
#pragma unroll
        for (int h = 0; h < 2; h++) {       // two k128 halves of the super-chunk
            const uint32_t saA = tb + s * STG + h * 32768;
            const uint32_t saW = tb + s * STG + OFF_W + h * 16384;
#pragma unroll
            for (int ks = 0; ks < 8; ks++) {
                uint32_t a4[4];
                uint32_t segA = (uint32_t)(ks * 2) + aSeg0;
                ldm4(a4, saA + aRow * 256 + physseg(segA, aXor) * 16);
#pragma unroll
                for (int q = 0; q < 2; q++) {
                    uint32_t b4[4];
                    uint32_t segB = (uint32_t)(ks * 2) + bSeg0;
                    ldm4(b4, saW + (bRow + q * 16) * 256 + physseg(segB, bXor) * 16);
                    mma16816(acc[2 * q],     a4, b4[0], b4[1]);
                    mma16816(acc[2 * q + 1], a4, b4[2], b4[3]);
                }
            }
        }
    }

    // ---- epilogue: acc[j] = gate j; thread owns 2 rows x 2 hids ----
    const int grp = lane >> 2, tig = lane & 3;
    const int hid0 = n_t * 16 + wn * 8 + 2 * tig;
#pragma unroll
    for (int s = 0; s < 2; s++) {
        int mm = m_t * 128 + wm * 16 + grp + 8 * s;
        float xv = xs ? xs[(size_t)mm * xs_stride] : 0.0f;
        float hn[2];
#pragma unroll
        for (int d = 0; d < 2; d++) {
            int e = 2 * s + d;
            int hd = hid0 + d;
            float pi = acc[0][e] + bias[hd]        + (wih ? xv * wih[hd]        : 0.f);
            float pf = acc[1][e] + bias[1024 + hd] + (wih ? xv * wih[1024 + hd] : 0.f);
            float pg = acc[2][e] + bias[2048 + hd] + (wih ? xv * wih[2048 + hd] : 0.f);
            float po = acc[3][e] + bias[3072 + hd] + (wih ? xv * wih[3072 + hd] : 0.f);
            size_t cix = (size_t)mm * Hdim + hd;
            float cn = sigmoidf_(pf) * cst[cix] + sigmoidf_(pi) * tanhf(pg);
            hn[d] = sigmoidf_(po) * tanhf(cn);
            cst[cix] = cn;
        }
        // write into swizzled A image: [chunk][m 0..255][256B]
        uint32_t c = (uint32_t)hid0 >> 7, koff = (uint32_t)hid0 & 127;
        size_t aoff = (size_t)((c * 256 + (uint32_t)mm) << 8)
                    + physseg(koff >> 3, (uint32_t)mm) * 16 + (koff & 7) * 2;
        __half h0 = __float2half_rn(hn[0]);
        __half h1 = __float2half_rn(hn[1]);
        *(uint32_t*)&oA[aoff] =
            (uint32_t)__half_as_ushort(h0) | ((uint32_t)__half_as_ushort(h1) << 16);
        if (of32) *(float2*)&of32[(size_t)mm * Hdim + hid0] = make_float2(hn[0], hn[1]);
    }
}

// Per-half FC: 8 CTAs of each half (ctaH<8), 16 warps each = 128 rows of own half.
__device__ __forceinline__ void fc_phase(
    const float* __restrict__ h1, const float* __restrict__ fcW,
    const float* __restrict__ fcb, float* __restrict__ out, int s)
{
    const int m_t = blockIdx.x & 1;
    const int ctaH = blockIdx.x >> 1;
    if (ctaH >= 8) return;
    int warp = threadIdx.x >> 5, lane = threadIdx.x & 31;
    int b = m_t * 128 + ctaH * 16 + warp;
    float sum = 0.0f;
    const float* hr = h1 + (size_t)b * Hdim;
#pragma unroll 8
    for (int k = lane; k < Hdim; k += 32) sum += hr[k] * fcW[k];
#pragma unroll
    for (int o = 16; o > 0; o >>= 1) sum += __shfl_down_sync(0xFFFFFFFFu, sum, o);
    if (lane == 0) {
        float y = sum + fcb[0];
        out[(size_t)b * OUTLEN + s] = y;
        g_xt[b] = y;
    }
}

__global__ void __launch_bounds__(NTHR, 1) lstm_mma_kernel(
    const float* __restrict__ x,
    const float* eWih0, const float* eWhh0, const float* eb0,
    const float* eWih1, const float* eWhh1, const float* eb1,
    const float* dWih0, const float* dWhh0, const float* db0,
    const float* dWih1, const float* dWhh1, const float* db1,
    const float* fcW, const float* fcb, float* __restrict__ out)
{
    extern __shared__ uint8_t dsm[];
    const uint32_t tb = smem_u32(dsm);
    const int m_t = blockIdx.x & 1;

    if (threadIdx.x == 0) {
        mbar_init(tb + MB_OFF + 0, 1);
        mbar_init(tb + MB_OFF + 8, 1);
    }
    const float* Ws[6] = { eWhh0, eWih1, eWhh1, dWhh0, dWih1, dWhh1 };
    prologue(Ws, x);
    gsync(2, NCTA);                         // full barrier: images + mbarrier init

    int par[NSTG] = { 0, 0 };
    int p0 = 0, p1 = 0;

#pragma unroll 1
    for (int t = 0; t < Tlen; t++) {
        lstm_phase(tb, 1,
            g_Aimg[0][p0], g_Wimg[0], nullptr, nullptr,
            eb0, eWih0, x + t, Tlen, g_c0,
            g_Aimg[0][p0 ^ 1], nullptr, par);
        p0 ^= 1;
        gsync(m_t, 64);
        lstm_phase(tb, 2,
            g_Aimg[0][p0], g_Wimg[1], g_Aimg[1][p1], g_Wimg[2],
            eb1, nullptr, nullptr, 0, g_c1,
            g_Aimg[1][p1 ^ 1], nullptr, par);
        p1 ^= 1;
        gsync(m_t, 64);
    }
#pragma unroll 1
    for (int s = 0; s < OUTLEN; s++) {
        lstm_phase(tb, 1,
            g_Aimg[0][p0], g_Wimg[3], nullptr, nullptr,
            db0, dWih0, g_xt, 1, g_c0,
            g_Aimg[0][p0 ^ 1], nullptr, par);
        p0 ^= 1;
        gsync(m_t, 64);
        lstm_phase(tb, 2,
            g_Aimg[0][p0], g_Wimg[4], g_Aimg[1][p1], g_Wimg[5],
            db1, nullptr, nullptr, 0, g_c1,
            g_Aimg[1][p1 ^ 1], g_h1f, par);
        p1 ^= 1;
        gsync(m_t, 64);
        fc_phase(g_h1f, fcW, fcb, out, s);
        gsync(m_t, 64);
    }
}

extern "C" void kernel_launch(void* const* d_in, const int* in_sizes, int n_in,
                              void* d_out, int out_size)
{
    (void)in_sizes; (void)n_in; (void)out_size;
    cudaFuncSetAttribute(lstm_mma_kernel, cudaFuncAttributeMaxDynamicSharedMemorySize, SMEM_TOTAL);
    lstm_mma_kernel<<<NCTA, NTHR, SMEM_TOTAL>>>(
        (const float*)d_in[0],
        (const float*)d_in[1],  (const float*)d_in[2],  (const float*)d_in[3],
        (const float*)d_in[4],  (const float*)d_in[5],  (const float*)d_in[6],
        (const float*)d_in[7],  (const float*)d_in[8],  (const float*)d_in[9],
        (const float*)d_in[10], (const float*)d_in[11], (const float*)d_in[12],
        (const float*)d_in[13], (const float*)d_in[14],
        (float*)d_out);
}